// round 1
// baseline (speedup 1.0000x reference)
#include <cuda_runtime.h>
#include <math.h>

// ---------------------------------------------------------------------------
// Problem constants (shapes & BOX_INFO are fixed by the reference)
// ---------------------------------------------------------------------------
#define HBG 512
#define WBG 512
#define IH  128
#define IW  128
#define NC  64
#define NINST 8
#define BIGV 100000.0f

// Scratch (device globals — allocation-free rule). Instance conv ping/pong
// reuses the larger bg buffers (instance intermediates are dead once the
// 1-channel instance masks are extracted).
__device__ float g_bg1[NC * HBG * WBG];       // 64 MB ping
__device__ float g_bg2[NC * HBG * WBG];       // 64 MB pong
__device__ float g_imask[NINST * IH * IW];    // 8 x 128x128 instance masks
__device__ float g_bgmask[HBG * WBG];         // 512x512 bg mask

// ---------------------------------------------------------------------------
// conv 3x3 SAME, Cin=64 -> Cout=64, +bias, ReLU.
// Block = 256 threads = one 16x16 output tile, all 64 output channels in regs.
// Input channels processed in chunks of 8 (smem: 8ch 18x18 tile + 8x64x9 wts).
// ---------------------------------------------------------------------------
__global__ __launch_bounds__(256)
void conv64(const float* __restrict__ in, const float* __restrict__ wgt,
            const float* __restrict__ bias, float* __restrict__ out,
            int Hh, int Ww)
{
    __shared__ __align__(16) float s_in[8 * 324];        // 8 ch x 18x18
    __shared__ __align__(16) float s_w [8 * 64 * 12];    // [ci][co][9 pad 12]

    const int tilesX = Ww >> 4;
    const int tX = blockIdx.x % tilesX;
    const int tY = blockIdx.x / tilesX;
    const int batch = blockIdx.y;
    const int tid = threadIdx.x;
    const int px = tid & 15, py = tid >> 4;
    const int ox = (tX << 4) + px, oy = (tY << 4) + py;
    const int chanStride = Hh * Ww;
    const float* inB = in + batch * NC * chanStride;

    float acc[64];
#pragma unroll
    for (int i = 0; i < 64; i++) acc[i] = 0.f;

    for (int cc = 0; cc < 8; cc++) {
        // load 8 input channels, 18x18 tile with halo, zero-padded (SAME)
        for (int idx = tid; idx < 8 * 324; idx += 256) {
            int ci = idx / 324;
            int r  = idx - ci * 324;
            int ry = r / 18, rx = r - ry * 18;
            int gy = (tY << 4) + ry - 1;
            int gx = (tX << 4) + rx - 1;
            float v = 0.f;
            if ((unsigned)gy < (unsigned)Hh && (unsigned)gx < (unsigned)Ww)
                v = inB[(cc * 8 + ci) * chanStride + gy * Ww + gx];
            s_in[idx] = v;
        }
        // load weights for this ci-chunk: wgt is OIHW [co][ci][3][3]
        for (int idx = tid; idx < 8 * 64 * 9; idx += 256) {
            int ci = idx / 576;
            int r  = idx - ci * 576;
            int co = r / 9, k = r - co * 9;
            s_w[ci * 768 + co * 12 + k] = wgt[(co * 64 + cc * 8 + ci) * 9 + k];
        }
        __syncthreads();

#pragma unroll 1
        for (int ci = 0; ci < 8; ci++) {
            const float* si = s_in + ci * 324 + py * 18 + px;
            float p0 = si[0],  p1 = si[1],  p2 = si[2];
            float p3 = si[18], p4 = si[19], p5 = si[20];
            float p6 = si[36], p7 = si[37], p8 = si[38];
            const float4* wp = reinterpret_cast<const float4*>(s_w + ci * 768);
#pragma unroll
            for (int co = 0; co < 64; co++) {
                float4 wa = wp[co * 3 + 0];
                float4 wb = wp[co * 3 + 1];
                float4 wc = wp[co * 3 + 2];
                acc[co] += wa.x * p0 + wa.y * p1 + wa.z * p2 + wa.w * p3
                         + wb.x * p4 + wb.y * p5 + wb.z * p6 + wb.w * p7
                         + wc.x * p8;
            }
        }
        __syncthreads();
    }

    float* outB = out + batch * NC * chanStride + oy * Ww + ox;
#pragma unroll
    for (int co = 0; co < 64; co++) {
        float v = acc[co] + bias[co];
        outB[co * chanStride] = v > 0.f ? v : 0.f;
    }
}

// ---------------------------------------------------------------------------
// conv 3x3 SAME, Cin=64 -> Cout=1, +bias, ReLU (the mask head)
// ---------------------------------------------------------------------------
__global__ __launch_bounds__(256)
void conv1out(const float* __restrict__ in, const float* __restrict__ wgt,
              const float* __restrict__ bias, float* __restrict__ out,
              int Hh, int Ww)
{
    __shared__ float s_in[8 * 324];
    __shared__ float sw[576];

    const int tilesX = Ww >> 4;
    const int tX = blockIdx.x % tilesX;
    const int tY = blockIdx.x / tilesX;
    const int batch = blockIdx.y;
    const int tid = threadIdx.x;
    const int px = tid & 15, py = tid >> 4;
    const int ox = (tX << 4) + px, oy = (tY << 4) + py;
    const int chanStride = Hh * Ww;
    const float* inB = in + batch * NC * chanStride;

    for (int idx = tid; idx < 576; idx += 256) sw[idx] = wgt[idx];

    float acc = 0.f;
    for (int cc = 0; cc < 8; cc++) {
        for (int idx = tid; idx < 8 * 324; idx += 256) {
            int ci = idx / 324;
            int r  = idx - ci * 324;
            int ry = r / 18, rx = r - ry * 18;
            int gy = (tY << 4) + ry - 1;
            int gx = (tX << 4) + rx - 1;
            float v = 0.f;
            if ((unsigned)gy < (unsigned)Hh && (unsigned)gx < (unsigned)Ww)
                v = inB[(cc * 8 + ci) * chanStride + gy * Ww + gx];
            s_in[idx] = v;
        }
        __syncthreads();
#pragma unroll
        for (int ci = 0; ci < 8; ci++) {
            const float* si = s_in + ci * 324 + py * 18 + px;
            const float* w9 = sw + (cc * 8 + ci) * 9;
            acc += w9[0] * si[0]  + w9[1] * si[1]  + w9[2] * si[2]
                 + w9[3] * si[18] + w9[4] * si[19] + w9[5] * si[20]
                 + w9[6] * si[36] + w9[7] * si[37] + w9[8] * si[38];
        }
        __syncthreads();
    }
    float v = acc + bias[0];
    out[batch * chanStride + oy * Ww + ox] = v > 0.f ? v : 0.f;
}

// ---------------------------------------------------------------------------
// Fused epilogue: per output pixel, bilinearly sample the 8 instance masks
// (half-pixel centers, clamped taps == jax.image.resize bilinear upsample),
// build the 9-way softmax (0 outside each box = the zero padding; bg gets
// +BIG outside the box union), then accumulate
//     out[c] = sum_i w_i * bilerp(inst_feat[i][c]) + w_bg * bg_feature[c]
// BOX_INFO is a compile-time constant of the problem -> hardcoded.
// ---------------------------------------------------------------------------
__global__ __launch_bounds__(256)
void fuse_out(const float* __restrict__ instf, const float* __restrict__ bgf,
              float* __restrict__ out)
{
    const int idx = blockIdx.x * 256 + threadIdx.x;   // 512*512 pixels
    const int x = idx & 511, y = idx >> 9;

    const int bl[8] = {0, 64, 128, 300, 64, 200, 32, 256};
    const int bt[8] = {0, 32, 256, 300, 128, 100, 256, 320};
    const int bw[8] = {256, 192, 320, 128, 384, 256, 160, 224};
    const int bh[8] = {256, 320, 192, 128, 256, 384, 224, 160};

    float m[8], W00[8], W01[8], W10[8], W11[8];
    int O00[8], O01[8], O10[8], O11[8];
    bool ins[8];
    bool uni = false;

#pragma unroll
    for (int i = 0; i < 8; i++) {
        int xl = x - bl[i], yt = y - bt[i];
        bool in_i = ((unsigned)xl < (unsigned)bw[i]) && ((unsigned)yt < (unsigned)bh[i]);
        ins[i] = in_i;
        uni |= in_i;
        float mi = 0.f, w00 = 0.f, w01 = 0.f, w10 = 0.f, w11 = 0.f;
        int o00 = 0, o01 = 0, o10 = 0, o11 = 0;
        if (in_i) {
            float sx = ((float)xl + 0.5f) * (128.f / (float)bw[i]) - 0.5f;
            float sy = ((float)yt + 0.5f) * (128.f / (float)bh[i]) - 0.5f;
            float fxf = floorf(sx), fyf = floorf(sy);
            float fx = sx - fxf, fy = sy - fyf;
            int x0 = (int)fxf, y0 = (int)fyf;
            int x0c = x0 < 0 ? 0 : x0;
            int x1c = (x0 + 1 > 127) ? 127 : (x0 + 1);
            int y0c = y0 < 0 ? 0 : y0;
            int y1c = (y0 + 1 > 127) ? 127 : (y0 + 1);
            o00 = y0c * 128 + x0c;  o01 = y0c * 128 + x1c;
            o10 = y1c * 128 + x0c;  o11 = y1c * 128 + x1c;
            w00 = (1.f - fx) * (1.f - fy);
            w01 = fx * (1.f - fy);
            w10 = (1.f - fx) * fy;
            w11 = fx * fy;
            const float* mp = g_imask + i * (IH * IW);
            mi = w00 * mp[o00] + w01 * mp[o01] + w10 * mp[o10] + w11 * mp[o11];
        }
        m[i] = mi;
        W00[i] = w00; W01[i] = w01; W10[i] = w10; W11[i] = w11;
        O00[i] = o00; O01[i] = o01; O10[i] = o10; O11[i] = o11;
    }

    float bgv = g_bgmask[idx] + (uni ? 0.f : BIGV);
    float mx = bgv;
#pragma unroll
    for (int i = 0; i < 8; i++) mx = fmaxf(mx, m[i]);

    float ebg = expf(bgv - mx);
    float s = ebg;
    float e[8];
#pragma unroll
    for (int i = 0; i < 8; i++) { e[i] = expf(m[i] - mx); s += e[i]; }
    float inv = 1.f / s;
    float wbg = ebg * inv;
#pragma unroll
    for (int i = 0; i < 8; i++) {
        float wi = e[i] * inv;
        W00[i] *= wi; W01[i] *= wi; W10[i] *= wi; W11[i] *= wi;
    }

    for (int c = 0; c < 64; c++) {
        float accv = wbg * bgf[(c << 18) + idx];
#pragma unroll
        for (int i = 0; i < 8; i++) {
            if (ins[i]) {
                const float* fp = instf + (((i << 6) + c) << 14);
                accv += W00[i] * fp[O00[i]] + W01[i] * fp[O01[i]]
                      + W10[i] * fp[O10[i]] + W11[i] * fp[O11[i]];
            }
        }
        out[(c << 18) + idx] = accv;
    }
}

// ---------------------------------------------------------------------------
// Launcher. Input order (metadata): instance_feature, bg_feature,
// iw1, ib1, iw2, ib2, iw3, ib3, bw1, bb1, bw2, bb2, bw3, bb3
// ---------------------------------------------------------------------------
extern "C" void kernel_launch(void* const* d_in, const int* in_sizes, int n_in,
                              void* d_out, int out_size)
{
    const float* instf = (const float*)d_in[0];
    const float* bgf   = (const float*)d_in[1];
    const float* iw1 = (const float*)d_in[2];
    const float* ib1 = (const float*)d_in[3];
    const float* iw2 = (const float*)d_in[4];
    const float* ib2 = (const float*)d_in[5];
    const float* iw3 = (const float*)d_in[6];
    const float* ib3 = (const float*)d_in[7];
    const float* bw1 = (const float*)d_in[8];
    const float* bb1 = (const float*)d_in[9];
    const float* bw2 = (const float*)d_in[10];
    const float* bb2 = (const float*)d_in[11];
    const float* bw3 = (const float*)d_in[12];
    const float* bb3 = (const float*)d_in[13];
    float* out = (float*)d_out;

    float *ga, *gb, *gim, *gbm;
    cudaGetSymbolAddress((void**)&ga,  g_bg1);
    cudaGetSymbolAddress((void**)&gb,  g_bg2);
    cudaGetSymbolAddress((void**)&gim, g_imask);
    cudaGetSymbolAddress((void**)&gbm, g_bgmask);

    // Instance block (8 images, 128x128) — reuses the big bg scratch buffers.
    conv64  <<<dim3(64, 8),   256>>>(instf, iw1, ib1, ga, IH, IW);
    conv64  <<<dim3(64, 8),   256>>>(ga,    iw2, ib2, gb, IH, IW);
    conv1out<<<dim3(64, 8),   256>>>(gb,    iw3, ib3, gim, IH, IW);

    // Background block (1 image, 512x512)
    conv64  <<<dim3(1024, 1), 256>>>(bgf, bw1, bb1, ga, HBG, WBG);
    conv64  <<<dim3(1024, 1), 256>>>(ga,  bw2, bb2, gb, HBG, WBG);
    conv1out<<<dim3(1024, 1), 256>>>(gb,  bw3, bb3, gbm, HBG, WBG);

    // Fused resize + softmax + weighted feature sum
    fuse_out<<<(HBG * WBG) / 256, 256>>>(instf, bgf, out);
}